// round 14
// baseline (speedup 1.0000x reference)
#include <cuda_runtime.h>
#include <math.h>
#include <stdint.h>

#define HEADS 2
#define KDIM 128
#define KNN 16
#define KNUM 512
#define HDIM 1024
#define BS 4096
#define QDIM (KDIM*2*HEADS)   // 512

// ---------------- scratch (static device globals; no allocation) ----------------
__device__ float d_q[BS*QDIM];              // 8 MB   q (pre+post LN, fp32)
__device__ float d_scores[4*BS*KNUM];       // 33.5 MB [hs][t][k]
__device__ float d_s1[4*BS*KNN];            // [hs][t][16]
__device__ int   d_i1[4*BS*KNN];
__device__ float d_w[BS*HEADS*KNN];         // softmax weights [t][h*16+j]
__device__ int   d_idx[BS*HEADS*KNN];       // combined indices
__device__ float d_mem[BS*HDIM];            // 16 MB
__device__ float d_hbuf[BS*HDIM];           // 16 MB

// =================================================================================
// FFMA SGEMM (selection path — BITWISE-FROZEN accumulation order):
//   C[M,N] = A[M,K] * B[N,K]^T, per-output strictly serial ascending-k FFMA chain.
//   SPLITK==1: two chains (k<K/2 into acc, k>=K/2 into acc2), C = fadd(acc,acc2)
//              == cublasLt split-K=2 rounding (the R11 passing order).
//   BM=128 fixed, BN in {64,128}; 256 threads; micro-tile 8 x (BN/16).
//   launch_bounds minBlocks=2 -> <=128 regs -> 2 CTAs/SM (occupancy fix).
// =================================================================================
template<int SPLITK, int BN>
__global__ __launch_bounds__(256, 2) void sgemm128(
    int M, int N, int K,
    const float* __restrict__ A, int lda, long long aBz,
    const float* __restrict__ B, int ldb, long long bBz,
    float* __restrict__ C, int ldc, long long cBz)
{
    constexpr int BK = 16;
    constexpr int TN = BN / 16;
    constexpr int BPASS = BN / 64;
    __shared__ float As[2][BK][132];
    __shared__ float Bs[2][BK][BN + 4];

    const int tid = threadIdx.x;
    const int tx = tid & 15, ty = tid >> 4;
    const int bm = blockIdx.y * 128, bn = blockIdx.x * BN;
    const int z = blockIdx.z;
    const float* Ab = A + (size_t)z * aBz;
    const float* Bb = B + (size_t)z * bBz;
    float*       Cb = C + (size_t)z * cBz;

    const int lr = tid >> 2, lc4 = (tid & 3) * 4;

    float acc[8][TN];
    float acc2[SPLITK ? 8 : 1][SPLITK ? TN : 1];
    #pragma unroll
    for (int i = 0; i < 8; i++)
        #pragma unroll
        for (int j = 0; j < TN; j++) acc[i][j] = 0.f;
    if (SPLITK) {
        #pragma unroll
        for (int i = 0; i < 8; i++)
            #pragma unroll
            for (int j = 0; j < TN; j++) acc2[i][j] = 0.f;
    }

    float4 pa0, pa1, pb[BPASS];

    auto gload = [&](int k0) {
        pa0 = *(const float4*)&Ab[(size_t)(bm + lr)      * lda + k0 + lc4];
        pa1 = *(const float4*)&Ab[(size_t)(bm + lr + 64) * lda + k0 + lc4];
        #pragma unroll
        for (int p = 0; p < BPASS; p++)
            pb[p] = *(const float4*)&Bb[(size_t)(bn + lr + p*64) * ldb + k0 + lc4];
    };
    auto sstore = [&](int buf) {
        As[buf][lc4+0][lr] = pa0.x; As[buf][lc4+1][lr] = pa0.y;
        As[buf][lc4+2][lr] = pa0.z; As[buf][lc4+3][lr] = pa0.w;
        As[buf][lc4+0][lr+64] = pa1.x; As[buf][lc4+1][lr+64] = pa1.y;
        As[buf][lc4+2][lr+64] = pa1.z; As[buf][lc4+3][lr+64] = pa1.w;
        #pragma unroll
        for (int p = 0; p < BPASS; p++) {
            Bs[buf][lc4+0][lr + p*64] = pb[p].x;
            Bs[buf][lc4+1][lr + p*64] = pb[p].y;
            Bs[buf][lc4+2][lr + p*64] = pb[p].z;
            Bs[buf][lc4+3][lr + p*64] = pb[p].w;
        }
    };

    gload(0); sstore(0); __syncthreads();
    const int nt = K / BK;
    const int ntHalf = nt >> 1;
    for (int t = 0; t < nt; t++) {
        const int buf = t & 1;
        if (t + 1 < nt) gload((t + 1) * BK);
        const bool second = SPLITK && (t >= ntHalf);
        #pragma unroll
        for (int kk = 0; kk < BK; kk++) {   // ascending k: one FFMA per output per k
            float av[8], bv[TN];
            *(float4*)&av[0] = *(const float4*)&As[buf][kk][ty*8];
            *(float4*)&av[4] = *(const float4*)&As[buf][kk][ty*8 + 4];
            *(float4*)&bv[0] = *(const float4*)&Bs[buf][kk][tx*TN];
            if (TN == 8)
                *(float4*)&bv[4] = *(const float4*)&Bs[buf][kk][tx*TN + 4];
            if (!second) {
                #pragma unroll
                for (int i = 0; i < 8; i++)
                    #pragma unroll
                    for (int j = 0; j < TN; j++)
                        acc[i][j] = __fmaf_rn(av[i], bv[j], acc[i][j]);
            } else {
                #pragma unroll
                for (int i = 0; i < 8; i++)
                    #pragma unroll
                    for (int j = 0; j < TN; j++)
                        acc2[i][j] = __fmaf_rn(av[i], bv[j], acc2[i][j]);
            }
        }
        if (t + 1 < nt) { sstore(buf ^ 1); }
        __syncthreads();
    }

    #pragma unroll
    for (int i = 0; i < 8; i++) {
        int row = bm + ty*8 + i;
        #pragma unroll
        for (int j = 0; j < TN; j++) {
            int col = bn + tx*TN + j;
            float v = acc[i][j];
            if (SPLITK) v = __fadd_rn(v, acc2[i][j]);
            Cb[(size_t)row * ldc + col] = v;
        }
    }
}

// =================================================================================
// TF32 tensor-core GEMM (gate/out path — smooth error only, ~2e-4):
//   C[M,N] = A[M,K] * B[N,K]^T via mma.sync.m16n8k8.tf32, fp32 accumulate.
//   EPI==1: C = silu(acc) * other
// =================================================================================
__device__ __forceinline__ uint32_t f2tf32(float x) {
    uint32_t u;
    asm("cvt.rna.tf32.f32 %0, %1;" : "=r"(u) : "f"(x));
    return u;
}

template<int EPI>
__global__ __launch_bounds__(256) void tf32gemm(
    int M, int N, int K,
    const float* __restrict__ A, int lda,
    const float* __restrict__ B, int ldb,
    float* __restrict__ C, int ldc,
    const float* __restrict__ other)
{
    constexpr int BK = 16;
    __shared__ uint32_t Asm[2][128][20];   // [m][k], pitch 20
    __shared__ uint32_t Bsm[2][BK][136];   // [k][n], pitch 136

    const int tid  = threadIdx.x;
    const int lane = tid & 31;
    const int wid  = tid >> 5;
    const int wm   = wid & 3;
    const int wn   = wid >> 2;
    const int r    = lane >> 2;
    const int c    = lane & 3;
    const int bm = blockIdx.y * 128, bn = blockIdx.x * 128;
    const int lr = tid >> 2, lc4 = (tid & 3) * 4;

    float d[2][8][4];
    #pragma unroll
    for (int mi = 0; mi < 2; mi++)
        #pragma unroll
        for (int nj = 0; nj < 8; nj++)
            #pragma unroll
            for (int q = 0; q < 4; q++) d[mi][nj][q] = 0.f;

    float4 fa0, fa1, fb0, fb1;
    auto gload = [&](int k0) {
        fa0 = *(const float4*)&A[(size_t)(bm + lr)      * lda + k0 + lc4];
        fa1 = *(const float4*)&A[(size_t)(bm + lr + 64) * lda + k0 + lc4];
        fb0 = *(const float4*)&B[(size_t)(bn + lr)      * ldb + k0 + lc4];
        fb1 = *(const float4*)&B[(size_t)(bn + lr + 64) * ldb + k0 + lc4];
    };
    auto sstore = [&](int buf) {
        uint4 ua0 = { f2tf32(fa0.x), f2tf32(fa0.y), f2tf32(fa0.z), f2tf32(fa0.w) };
        uint4 ua1 = { f2tf32(fa1.x), f2tf32(fa1.y), f2tf32(fa1.z), f2tf32(fa1.w) };
        *(uint4*)&Asm[buf][lr][lc4]      = ua0;
        *(uint4*)&Asm[buf][lr + 64][lc4] = ua1;
        Bsm[buf][lc4+0][lr] = f2tf32(fb0.x);
        Bsm[buf][lc4+1][lr] = f2tf32(fb0.y);
        Bsm[buf][lc4+2][lr] = f2tf32(fb0.z);
        Bsm[buf][lc4+3][lr] = f2tf32(fb0.w);
        Bsm[buf][lc4+0][lr+64] = f2tf32(fb1.x);
        Bsm[buf][lc4+1][lr+64] = f2tf32(fb1.y);
        Bsm[buf][lc4+2][lr+64] = f2tf32(fb1.z);
        Bsm[buf][lc4+3][lr+64] = f2tf32(fb1.w);
    };

    gload(0); sstore(0); __syncthreads();
    const int nt = K / BK;
    for (int t = 0; t < nt; t++) {
        const int buf = t & 1;
        if (t + 1 < nt) gload((t + 1) * BK);
        #pragma unroll
        for (int ks = 0; ks < BK; ks += 8) {
            uint32_t afr[2][4], bfr[8][2];
            #pragma unroll
            for (int mi = 0; mi < 2; mi++) {
                int m0 = wm*32 + mi*16;
                afr[mi][0] = Asm[buf][m0 + r    ][ks + c];
                afr[mi][1] = Asm[buf][m0 + r + 8][ks + c];
                afr[mi][2] = Asm[buf][m0 + r    ][ks + c + 4];
                afr[mi][3] = Asm[buf][m0 + r + 8][ks + c + 4];
            }
            #pragma unroll
            for (int nj = 0; nj < 8; nj++) {
                int n0 = wn*64 + nj*8 + r;
                bfr[nj][0] = Bsm[buf][ks + c    ][n0];
                bfr[nj][1] = Bsm[buf][ks + c + 4][n0];
            }
            #pragma unroll
            for (int mi = 0; mi < 2; mi++)
                #pragma unroll
                for (int nj = 0; nj < 8; nj++) {
                    asm volatile(
                        "mma.sync.aligned.m16n8k8.row.col.f32.tf32.tf32.f32 "
                        "{%0,%1,%2,%3}, {%4,%5,%6,%7}, {%8,%9}, {%0,%1,%2,%3};"
                        : "+f"(d[mi][nj][0]), "+f"(d[mi][nj][1]),
                          "+f"(d[mi][nj][2]), "+f"(d[mi][nj][3])
                        : "r"(afr[mi][0]), "r"(afr[mi][1]),
                          "r"(afr[mi][2]), "r"(afr[mi][3]),
                          "r"(bfr[nj][0]), "r"(bfr[nj][1]));
                }
        }
        if (t + 1 < nt) { sstore(buf ^ 1); }
        __syncthreads();
    }

    #pragma unroll
    for (int mi = 0; mi < 2; mi++) {
        #pragma unroll
        for (int nj = 0; nj < 8; nj++) {
            int col = bn + wn*64 + nj*8 + c*2;
            #pragma unroll
            for (int half = 0; half < 2; half++) {
                int row = bm + wm*32 + mi*16 + r + half*8;
                float v0 = d[mi][nj][half*2 + 0];
                float v1 = d[mi][nj][half*2 + 1];
                if (EPI == 1) {
                    const float2 o = *(const float2*)&other[(size_t)row * ldc + col];
                    float s0 = v0 / (1.0f + expf(-v0));
                    float s1 = v1 / (1.0f + expf(-v1));
                    v0 = s0 * o.x;
                    v1 = s1 * o.y;
                }
                float2 res = { v0, v1 };
                *(float2*)&C[(size_t)row * ldc + col] = res;
            }
        }
    }
}

// ---------------- per-128 LayerNorm (XLA row-reduction order) — BITWISE-FROZEN ---
__global__ __launch_bounds__(256) void qln_kernel(const float* __restrict__ gamma)
{
    __shared__ float s_w[4][2];
    int tid = threadIdx.x;
    int r = tid >> 6;
    int tx = tid & 63;
    int lane = tid & 31;
    int wIn = (tid >> 5) & 1;
    size_t row = (size_t)blockIdx.x * 4 + r;
    float* p = d_q + row * 128;
    float x0 = p[2*tx], x1 = p[2*tx+1];

    float part = __fadd_rn(x0, x1);
    #pragma unroll
    for (int o = 16; o; o >>= 1)
        part = __fadd_rn(part, __shfl_down_sync(0xffffffffu, part, o));
    if (lane == 0) s_w[r][wIn] = part;
    __syncthreads();
    float mu = __fmul_rn(__fadd_rn(s_w[r][0], s_w[r][1]), 1.0f/128.0f);
    __syncthreads();

    float d0 = __fsub_rn(x0, mu), d1 = __fsub_rn(x1, mu);
    float vp = __fadd_rn(__fmul_rn(d0, d0), __fmul_rn(d1, d1));
    #pragma unroll
    for (int o = 16; o; o >>= 1)
        vp = __fadd_rn(vp, __shfl_down_sync(0xffffffffu, vp, o));
    if (lane == 0) s_w[r][wIn] = vp;
    __syncthreads();
    float var = __fmul_rn(__fadd_rn(s_w[r][0], s_w[r][1]), 1.0f/128.0f);

    float denom = __fsqrt_rn(__fadd_rn(var, 1e-5f));
    p[2*tx]   = __fmul_rn(__fdiv_rn(d0, denom), gamma[2*tx]);
    p[2*tx+1] = __fmul_rn(__fdiv_rn(d1, denom), gamma[2*tx+1]);
}

// ---------------- top-16 of 512 (one warp per instance) — BITWISE-FROZEN ---------
__global__ void topk1_kernel()
{
    int gw = (blockIdx.x * blockDim.x + threadIdx.x) >> 5;
    int lane = threadIdx.x & 31;
    if (gw >= 4 * BS) return;
    const float* s = d_scores + (size_t)gw * 512;
    float v[16];
    #pragma unroll
    for (int j = 0; j < 16; j++) v[j] = s[lane + j * 32];
    float* os = d_s1 + (size_t)gw * 16;
    int*   oi = d_i1 + (size_t)gw * 16;
    for (int it = 0; it < 16; it++) {
        float bv = -INFINITY; int bj = 0;
        #pragma unroll
        for (int j = 0; j < 16; j++)
            if (v[j] > bv) { bv = v[j]; bj = j; }
        int bidx = lane + bj * 32;
        #pragma unroll
        for (int o = 16; o; o >>= 1) {
            float ov = __shfl_xor_sync(0xffffffffu, bv, o);
            int oid = __shfl_xor_sync(0xffffffffu, bidx, o);
            if (ov > bv || (ov == bv && oid < bidx)) { bv = ov; bidx = oid; }
        }
        if (lane == 0) { os[it] = bv; oi[it] = bidx; }
        #pragma unroll
        for (int j = 0; j < 16; j++)
            if (lane + j * 32 == bidx) v[j] = -INFINITY;
    }
}

// ---------------- combine, top-16 of 256, softmax — BITWISE-FROZEN ---------------
__global__ void topk2_kernel()
{
    __shared__ float sh_s1[8][16], sh_s2[8][16], sh_sel[8][16];
    __shared__ int   sh_i1[8][16], sh_i2[8][16];
    int wIn = threadIdx.x >> 5, lane = threadIdx.x & 31;
    int inst = blockIdx.x * 8 + wIn;
    int t = inst >> 1, h = inst & 1;
    int hs1 = h * 2 + 0, hs2 = h * 2 + 1;
    if (lane < 16) {
        sh_s1[wIn][lane] = d_s1[((size_t)hs1 * BS + t) * 16 + lane];
        sh_i1[wIn][lane] = d_i1[((size_t)hs1 * BS + t) * 16 + lane];
        sh_s2[wIn][lane] = d_s1[((size_t)hs2 * BS + t) * 16 + lane];
        sh_i2[wIn][lane] = d_i1[((size_t)hs2 * BS + t) * 16 + lane];
    }
    __syncwarp();
    float v[8];
    #pragma unroll
    for (int j = 0; j < 8; j++) {
        int c = lane + j * 32;
        v[j] = __fadd_rn(sh_s1[wIn][c >> 4], sh_s2[wIn][c & 15]);
    }
    int wbase = t * (HEADS * KNN) + h * KNN;
    for (int it = 0; it < 16; it++) {
        float bv = -INFINITY; int bj = 0;
        #pragma unroll
        for (int j = 0; j < 8; j++)
            if (v[j] > bv) { bv = v[j]; bj = j; }
        int bc = lane + bj * 32;
        #pragma unroll
        for (int o = 16; o; o >>= 1) {
            float ov = __shfl_xor_sync(0xffffffffu, bv, o);
            int oc = __shfl_xor_sync(0xffffffffu, bc, o);
            if (ov > bv || (ov == bv && oc < bc)) { bv = ov; bc = oc; }
        }
        if (lane == 0) {
            sh_sel[wIn][it] = bv;
            d_idx[wbase + it] = sh_i1[wIn][bc >> 4] * KNUM + sh_i2[wIn][bc & 15];
        }
        #pragma unroll
        for (int j = 0; j < 8; j++)
            if (lane + j * 32 == bc) v[j] = -INFINITY;
    }
    __syncwarp();
    if (lane < 16) {
        float m = sh_sel[wIn][0];
        float e = expf(__fsub_rn(sh_sel[wIn][lane], m));
        float s = e;
        #pragma unroll
        for (int o = 8; o; o >>= 1) s = __fadd_rn(s, __shfl_xor_sync(0x0000ffffu, s, o));
        d_w[wbase + lane] = __fdiv_rn(e, s);
    }
}

// ---------------- gather + weighted sum over values_table (fp32) -----------------
__global__ __launch_bounds__(256) void gather_kernel(const float* __restrict__ vt)
{
    int t = blockIdx.x;
    __shared__ float w[32];
    __shared__ int idx[32];
    if (threadIdx.x < 32) {
        w[threadIdx.x] = d_w[t * 32 + threadIdx.x];
        idx[threadIdx.x] = d_idx[t * 32 + threadIdx.x];
    }
    __syncthreads();
    const float4* vt4 = (const float4*)vt;
    int d = threadIdx.x;
    float4 acc = {0.f, 0.f, 0.f, 0.f};
    #pragma unroll 4
    for (int e = 0; e < 32; e++) {
        float4 r = vt4[(size_t)idx[e] * 256 + d];
        float ww = w[e];
        acc.x = __fmaf_rn(ww, r.x, acc.x);
        acc.y = __fmaf_rn(ww, r.y, acc.y);
        acc.z = __fmaf_rn(ww, r.z, acc.z);
        acc.w = __fmaf_rn(ww, r.w, acc.w);
    }
    ((float4*)d_mem)[(size_t)t * 256 + d] = acc;
}

// ---------------- launch ----------------
extern "C" void kernel_launch(void* const* d_in, const int* in_sizes, int n_in,
                              void* d_out, int out_size)
{
    const float* x    = (const float*)d_in[0];   // [4096,1024]
    const float* wq   = (const float*)d_in[1];   // [512,1024]
    const float* qnw  = (const float*)d_in[2];   // [128]
    const float* keys = (const float*)d_in[3];   // [2,2,512,128]
    const float* vt   = (const float*)d_in[4];   // [262144,1024]
    const float* wsw  = (const float*)d_in[5];   // [1024,1024]
    const float* wv   = (const float*)d_in[6];   // [1024,1024]
    float* out = (float*)d_out;

    float *pq, *pscores, *pmem, *phbuf;
    cudaGetSymbolAddress((void**)&pq,      d_q);
    cudaGetSymbolAddress((void**)&pscores, d_scores);
    cudaGetSymbolAddress((void**)&pmem,    d_mem);
    cudaGetSymbolAddress((void**)&phbuf,   d_hbuf);

    // 1. q = x @ wq^T (4096x512, K=1024) -- split-K=2 in ONE kernel (two serial
    //    chains, final fadd) == R11 bitwise order, no intermediate round-trip.
    sgemm128<1,64><<<dim3(QDIM/64, BS/128, 1), 256>>>(
        BS, QDIM, HDIM, x, HDIM, 0, wq, HDIM, 0, pq, QDIM, 0);

    // 2. per-128 layernorm (XLA order) -- frozen
    qln_kernel<<<(BS*4)/4, 256>>>(qnw);

    // 3. scores[hs] = q[:,hs*128:..] @ keys[hs]^T, serial-k, batched over z=4
    sgemm128<0,128><<<dim3(KNUM/128, BS/128, 4), 256>>>(
        BS, KNUM, KDIM,
        pq, QDIM, (long long)KDIM,
        keys, KDIM, (long long)KNUM*KDIM,
        pscores, KNUM, (long long)BS*KNUM);

    // 4. top-16 of 512 per (t,h,s)
    topk1_kernel<<<(4*BS*32)/256, 256>>>();

    // 5. combine + top-16 of 256 + softmax per (t,h)
    topk2_kernel<<<(BS*HEADS)/8, 256>>>();

    // 6. gather weighted values
    gather_kernel<<<BS, 256>>>(vt);

    // 7. hbuf = silu(x @ wsw^T) * mem -- TF32 tensor cores
    tf32gemm<1><<<dim3(HDIM/128, BS/128), 256>>>(
        BS, HDIM, HDIM, x, HDIM, wsw, HDIM, phbuf, HDIM, pmem);

    // 8. out = hbuf @ wv^T -- TF32 tensor cores
    tf32gemm<0><<<dim3(HDIM/128, BS/128), 256>>>(
        BS, HDIM, HDIM, phbuf, HDIM, wv, HDIM, out, HDIM, nullptr);
}

// round 16
// speedup vs baseline: 1.0495x; 1.0495x over previous
#include <cuda_runtime.h>
#include <math.h>
#include <stdint.h>

#define HEADS 2
#define KDIM 128
#define KNN 16
#define KNUM 512
#define HDIM 1024
#define BS 4096
#define QDIM (KDIM*2*HEADS)   // 512

__device__ float d_q[BS*QDIM];
__device__ float d_scores[4*BS*KNUM];
__device__ float d_s1[4*BS*KNN];
__device__ int   d_i1[4*BS*KNN];
__device__ float d_w[BS*HEADS*KNN];
__device__ int   d_idx[BS*HEADS*KNN];
__device__ float d_mem[BS*HDIM];
__device__ float d_hbuf[BS*HDIM];

// =================================================================================
// FFMA SGEMM (selection path — BITWISE-FROZEN accumulation order).
// Inner product now uses fma.rn.f32x2: each half is an exact IEEE fp32 FMA, so the
// per-output serial ascending-k chain is bitwise identical to scalar FFMA; two
// adjacent N outputs share one instruction (2x FMA-pipe throughput).
// SPLITK==1: two chains (k<K/2, k>=K/2), C = fadd(acc, acc2)  [R11 passing order]
// =================================================================================
template<int SPLITK, int BN>
__global__ __launch_bounds__(256, 2) void sgemm128(
    int M, int N, int K,
    const float* __restrict__ A, int lda, long long aBz,
    const float* __restrict__ B, int ldb, long long bBz,
    float* __restrict__ C, int ldc, long long cBz)
{
    constexpr int BK = 16;
    constexpr int TN = BN / 16;
    constexpr int TNP = TN / 2;
    constexpr int BPASS = BN / 64;
    __shared__ __align__(16) float As[2][BK][132];
    __shared__ __align__(16) float Bs[2][BK][BN + 4];

    const int tid = threadIdx.x;
    const int tx = tid & 15, ty = tid >> 4;
    const int bm = blockIdx.y * 128, bn = blockIdx.x * BN;
    const int z = blockIdx.z;
    const float* Ab = A + (size_t)z * aBz;
    const float* Bb = B + (size_t)z * bBz;
    float*       Cb = C + (size_t)z * cBz;
    const int lr = tid >> 2, lc4 = (tid & 3) * 4;

    unsigned long long acc[8][TNP];
    unsigned long long acc2[SPLITK ? 8 : 1][SPLITK ? TNP : 1];
    #pragma unroll
    for (int i = 0; i < 8; i++)
        #pragma unroll
        for (int p = 0; p < TNP; p++) acc[i][p] = 0ull;
    if (SPLITK) {
        #pragma unroll
        for (int i = 0; i < 8; i++)
            #pragma unroll
            for (int p = 0; p < TNP; p++) acc2[i][p] = 0ull;
    }

    float4 pa0, pa1, pb[BPASS];
    auto gload = [&](int k0) {
        pa0 = *(const float4*)&Ab[(size_t)(bm + lr)      * lda + k0 + lc4];
        pa1 = *(const float4*)&Ab[(size_t)(bm + lr + 64) * lda + k0 + lc4];
        #pragma unroll
        for (int p = 0; p < BPASS; p++)
            pb[p] = *(const float4*)&Bb[(size_t)(bn + lr + p*64) * ldb + k0 + lc4];
    };
    auto sstore = [&](int buf) {
        As[buf][lc4+0][lr] = pa0.x; As[buf][lc4+1][lr] = pa0.y;
        As[buf][lc4+2][lr] = pa0.z; As[buf][lc4+3][lr] = pa0.w;
        As[buf][lc4+0][lr+64] = pa1.x; As[buf][lc4+1][lr+64] = pa1.y;
        As[buf][lc4+2][lr+64] = pa1.z; As[buf][lc4+3][lr+64] = pa1.w;
        #pragma unroll
        for (int p = 0; p < BPASS; p++) {
            Bs[buf][lc4+0][lr + p*64] = pb[p].x;
            Bs[buf][lc4+1][lr + p*64] = pb[p].y;
            Bs[buf][lc4+2][lr + p*64] = pb[p].z;
            Bs[buf][lc4+3][lr + p*64] = pb[p].w;
        }
    };

    gload(0); sstore(0); __syncthreads();
    const int nt = K / BK;
    const int ntHalf = nt >> 1;
    for (int t = 0; t < nt; t++) {
        const int buf = t & 1;
        if (t + 1 < nt) gload((t + 1) * BK);
        const bool second = SPLITK && (t >= ntHalf);
        #pragma unroll
        for (int kk = 0; kk < BK; kk++) {   // ascending k
            float av[8];
            *(float4*)&av[0] = *(const float4*)&As[buf][kk][ty*8];
            *(float4*)&av[4] = *(const float4*)&As[buf][kk][ty*8 + 4];
            unsigned long long ap[8];
            #pragma unroll
            for (int i = 0; i < 8; i++)
                asm("mov.b64 %0, {%1, %1};" : "=l"(ap[i]) : "r"(__float_as_uint(av[i])));
            unsigned long long bp[TNP];
            const unsigned long long* bq =
                reinterpret_cast<const unsigned long long*>(&Bs[buf][kk][tx*TN]);
            #pragma unroll
            for (int p = 0; p < TNP; p++) bp[p] = bq[p];
            if (!second) {
                #pragma unroll
                for (int i = 0; i < 8; i++)
                    #pragma unroll
                    for (int p = 0; p < TNP; p++)
                        asm("fma.rn.f32x2 %0, %1, %2, %0;"
                            : "+l"(acc[i][p]) : "l"(ap[i]), "l"(bp[p]));
            } else {
                #pragma unroll
                for (int i = 0; i < 8; i++)
                    #pragma unroll
                    for (int p = 0; p < TNP; p++)
                        asm("fma.rn.f32x2 %0, %1, %2, %0;"
                            : "+l"(acc2[i][p]) : "l"(ap[i]), "l"(bp[p]));
            }
        }
        if (t + 1 < nt) { sstore(buf ^ 1); }
        __syncthreads();
    }

    #pragma unroll
    for (int i = 0; i < 8; i++) {
        int row = bm + ty*8 + i;
        #pragma unroll
        for (int p = 0; p < TNP; p++) {
            int col = bn + tx*TN + 2*p;
            float2 f = *(float2*)&acc[i][p];
            if (SPLITK) {
                float2 g = *(float2*)&acc2[i][p];
                f.x = __fadd_rn(f.x, g.x);
                f.y = __fadd_rn(f.y, g.y);
            }
            *(float2*)&Cb[(size_t)row * ldc + col] = f;
        }
    }
}

// ================= TF32 tensor-core GEMM (gate/out; smooth ~2e-4) ================
__device__ __forceinline__ uint32_t f2tf32(float x) {
    uint32_t u;
    asm("cvt.rna.tf32.f32 %0, %1;" : "=r"(u) : "f"(x));
    return u;
}

template<int EPI>
__global__ __launch_bounds__(256) void tf32gemm(
    int M, int N, int K,
    const float* __restrict__ A, int lda,
    const float* __restrict__ B, int ldb,
    float* __restrict__ C, int ldc,
    const float* __restrict__ other)
{
    constexpr int BK = 16;
    __shared__ uint32_t Asm[2][128][20];
    __shared__ uint32_t Bsm[2][BK][136];

    const int tid  = threadIdx.x;
    const int lane = tid & 31;
    const int wid  = tid >> 5;
    const int wm   = wid & 3;
    const int wn   = wid >> 2;
    const int r    = lane >> 2;
    const int c    = lane & 3;
    const int bm = blockIdx.y * 128, bn = blockIdx.x * 128;
    const int lr = tid >> 2, lc4 = (tid & 3) * 4;

    float d[2][8][4];
    #pragma unroll
    for (int mi = 0; mi < 2; mi++)
        #pragma unroll
        for (int nj = 0; nj < 8; nj++)
            #pragma unroll
            for (int q = 0; q < 4; q++) d[mi][nj][q] = 0.f;

    float4 fa0, fa1, fb0, fb1;
    auto gload = [&](int k0) {
        fa0 = *(const float4*)&A[(size_t)(bm + lr)      * lda + k0 + lc4];
        fa1 = *(const float4*)&A[(size_t)(bm + lr + 64) * lda + k0 + lc4];
        fb0 = *(const float4*)&B[(size_t)(bn + lr)      * ldb + k0 + lc4];
        fb1 = *(const float4*)&B[(size_t)(bn + lr + 64) * ldb + k0 + lc4];
    };
    auto sstore = [&](int buf) {
        uint4 ua0 = { f2tf32(fa0.x), f2tf32(fa0.y), f2tf32(fa0.z), f2tf32(fa0.w) };
        uint4 ua1 = { f2tf32(fa1.x), f2tf32(fa1.y), f2tf32(fa1.z), f2tf32(fa1.w) };
        *(uint4*)&Asm[buf][lr][lc4]      = ua0;
        *(uint4*)&Asm[buf][lr + 64][lc4] = ua1;
        Bsm[buf][lc4+0][lr] = f2tf32(fb0.x);
        Bsm[buf][lc4+1][lr] = f2tf32(fb0.y);
        Bsm[buf][lc4+2][lr] = f2tf32(fb0.z);
        Bsm[buf][lc4+3][lr] = f2tf32(fb0.w);
        Bsm[buf][lc4+0][lr+64] = f2tf32(fb1.x);
        Bsm[buf][lc4+1][lr+64] = f2tf32(fb1.y);
        Bsm[buf][lc4+2][lr+64] = f2tf32(fb1.z);
        Bsm[buf][lc4+3][lr+64] = f2tf32(fb1.w);
    };

    gload(0); sstore(0); __syncthreads();
    const int nt = K / BK;
    for (int t = 0; t < nt; t++) {
        const int buf = t & 1;
        if (t + 1 < nt) gload((t + 1) * BK);
        #pragma unroll
        for (int ks = 0; ks < BK; ks += 8) {
            uint32_t afr[2][4], bfr[8][2];
            #pragma unroll
            for (int mi = 0; mi < 2; mi++) {
                int m0 = wm*32 + mi*16;
                afr[mi][0] = Asm[buf][m0 + r    ][ks + c];
                afr[mi][1] = Asm[buf][m0 + r + 8][ks + c];
                afr[mi][2] = Asm[buf][m0 + r    ][ks + c + 4];
                afr[mi][3] = Asm[buf][m0 + r + 8][ks + c + 4];
            }
            #pragma unroll
            for (int nj = 0; nj < 8; nj++) {
                int n0 = wn*64 + nj*8 + r;
                bfr[nj][0] = Bsm[buf][ks + c    ][n0];
                bfr[nj][1] = Bsm[buf][ks + c + 4][n0];
            }
            #pragma unroll
            for (int mi = 0; mi < 2; mi++)
                #pragma unroll
                for (int nj = 0; nj < 8; nj++) {
                    asm volatile(
                        "mma.sync.aligned.m16n8k8.row.col.f32.tf32.tf32.f32 "
                        "{%0,%1,%2,%3}, {%4,%5,%6,%7}, {%8,%9}, {%0,%1,%2,%3};"
                        : "+f"(d[mi][nj][0]), "+f"(d[mi][nj][1]),
                          "+f"(d[mi][nj][2]), "+f"(d[mi][nj][3])
                        : "r"(afr[mi][0]), "r"(afr[mi][1]),
                          "r"(afr[mi][2]), "r"(afr[mi][3]),
                          "r"(bfr[nj][0]), "r"(bfr[nj][1]));
                }
        }
        if (t + 1 < nt) { sstore(buf ^ 1); }
        __syncthreads();
    }

    #pragma unroll
    for (int mi = 0; mi < 2; mi++) {
        #pragma unroll
        for (int nj = 0; nj < 8; nj++) {
            int col = bn + wn*64 + nj*8 + c*2;
            #pragma unroll
            for (int half = 0; half < 2; half++) {
                int row = bm + wm*32 + mi*16 + r + half*8;
                float v0 = d[mi][nj][half*2 + 0];
                float v1 = d[mi][nj][half*2 + 1];
                if (EPI == 1) {
                    const float2 o = *(const float2*)&other[(size_t)row * ldc + col];
                    float s0 = v0 / (1.0f + expf(-v0));
                    float s1 = v1 / (1.0f + expf(-v1));
                    v0 = s0 * o.x;
                    v1 = s1 * o.y;
                }
                float2 res = { v0, v1 };
                *(float2*)&C[(size_t)row * ldc + col] = res;
            }
        }
    }
}

// ------------- per-128 LayerNorm (XLA order) — BITWISE-FROZEN --------------------
__global__ __launch_bounds__(256) void qln_kernel(const float* __restrict__ gamma)
{
    __shared__ float s_w[4][2];
    int tid = threadIdx.x;
    int r = tid >> 6;
    int tx = tid & 63;
    int lane = tid & 31;
    int wIn = (tid >> 5) & 1;
    size_t row = (size_t)blockIdx.x * 4 + r;
    float* p = d_q + row * 128;
    float x0 = p[2*tx], x1 = p[2*tx+1];

    float part = __fadd_rn(x0, x1);
    #pragma unroll
    for (int o = 16; o; o >>= 1)
        part = __fadd_rn(part, __shfl_down_sync(0xffffffffu, part, o));
    if (lane == 0) s_w[r][wIn] = part;
    __syncthreads();
    float mu = __fmul_rn(__fadd_rn(s_w[r][0], s_w[r][1]), 1.0f/128.0f);
    __syncthreads();

    float d0 = __fsub_rn(x0, mu), d1 = __fsub_rn(x1, mu);
    float vp = __fadd_rn(__fmul_rn(d0, d0), __fmul_rn(d1, d1));
    #pragma unroll
    for (int o = 16; o; o >>= 1)
        vp = __fadd_rn(vp, __shfl_down_sync(0xffffffffu, vp, o));
    if (lane == 0) s_w[r][wIn] = vp;
    __syncthreads();
    float var = __fmul_rn(__fadd_rn(s_w[r][0], s_w[r][1]), 1.0f/128.0f);

    float denom = __fsqrt_rn(__fadd_rn(var, 1e-5f));
    p[2*tx]   = __fmul_rn(__fdiv_rn(d0, denom), gamma[2*tx]);
    p[2*tx+1] = __fmul_rn(__fdiv_rn(d1, denom), gamma[2*tx+1]);
}

// ------------- top-16 of 512 (one warp per instance) — BITWISE-FROZEN ------------
__global__ void topk1_kernel()
{
    int gw = (blockIdx.x * blockDim.x + threadIdx.x) >> 5;
    int lane = threadIdx.x & 31;
    if (gw >= 4 * BS) return;
    const float* s = d_scores + (size_t)gw * 512;
    float v[16];
    #pragma unroll
    for (int j = 0; j < 16; j++) v[j] = s[lane + j * 32];
    float* os = d_s1 + (size_t)gw * 16;
    int*   oi = d_i1 + (size_t)gw * 16;
    for (int it = 0; it < 16; it++) {
        float bv = -INFINITY; int bj = 0;
        #pragma unroll
        for (int j = 0; j < 16; j++)
            if (v[j] > bv) { bv = v[j]; bj = j; }
        int bidx = lane + bj * 32;
        #pragma unroll
        for (int o = 16; o; o >>= 1) {
            float ov = __shfl_xor_sync(0xffffffffu, bv, o);
            int oid = __shfl_xor_sync(0xffffffffu, bidx, o);
            if (ov > bv || (ov == bv && oid < bidx)) { bv = ov; bidx = oid; }
        }
        if (lane == 0) { os[it] = bv; oi[it] = bidx; }
        #pragma unroll
        for (int j = 0; j < 16; j++)
            if (lane + j * 32 == bidx) v[j] = -INFINITY;
    }
}

// ------------- combine, top-16 of 256, softmax — BITWISE-FROZEN ------------------
__global__ void topk2_kernel()
{
    __shared__ float sh_s1[8][16], sh_s2[8][16], sh_sel[8][16];
    __shared__ int   sh_i1[8][16], sh_i2[8][16];
    int wIn = threadIdx.x >> 5, lane = threadIdx.x & 31;
    int inst = blockIdx.x * 8 + wIn;
    int t = inst >> 1, h = inst & 1;
    int hs1 = h * 2 + 0, hs2 = h * 2 + 1;
    if (lane < 16) {
        sh_s1[wIn][lane] = d_s1[((size_t)hs1 * BS + t) * 16 + lane];
        sh_i1[wIn][lane] = d_i1[((size_t)hs1 * BS + t) * 16 + lane];
        sh_s2[wIn][lane] = d_s1[((size_t)hs2 * BS + t) * 16 + lane];
        sh_i2[wIn][lane] = d_i1[((size_t)hs2 * BS + t) * 16 + lane];
    }
    __syncwarp();
    float v[8];
    #pragma unroll
    for (int j = 0; j < 8; j++) {
        int c = lane + j * 32;
        v[j] = __fadd_rn(sh_s1[wIn][c >> 4], sh_s2[wIn][c & 15]);
    }
    int wbase = t * (HEADS * KNN) + h * KNN;
    for (int it = 0; it < 16; it++) {
        float bv = -INFINITY; int bj = 0;
        #pragma unroll
        for (int j = 0; j < 8; j++)
            if (v[j] > bv) { bv = v[j]; bj = j; }
        int bc = lane + bj * 32;
        #pragma unroll
        for (int o = 16; o; o >>= 1) {
            float ov = __shfl_xor_sync(0xffffffffu, bv, o);
            int oc = __shfl_xor_sync(0xffffffffu, bc, o);
            if (ov > bv || (ov == bv && oc < bc)) { bv = ov; bc = oc; }
        }
        if (lane == 0) {
            sh_sel[wIn][it] = bv;
            d_idx[wbase + it] = sh_i1[wIn][bc >> 4] * KNUM + sh_i2[wIn][bc & 15];
        }
        #pragma unroll
        for (int j = 0; j < 8; j++)
            if (lane + j * 32 == bc) v[j] = -INFINITY;
    }
    __syncwarp();
    if (lane < 16) {
        float m = sh_sel[wIn][0];
        float e = expf(__fsub_rn(sh_sel[wIn][lane], m));
        float s = e;
        #pragma unroll
        for (int o = 8; o; o >>= 1) s = __fadd_rn(s, __shfl_xor_sync(0x0000ffffu, s, o));
        d_w[wbase + lane] = __fdiv_rn(e, s);
    }
}

// ------------- gather + weighted sum over values_table ---------------------------
__global__ __launch_bounds__(256) void gather_kernel(const float* __restrict__ vt)
{
    int t = blockIdx.x;
    __shared__ float w[32];
    __shared__ int idx[32];
    if (threadIdx.x < 32) {
        w[threadIdx.x] = d_w[t * 32 + threadIdx.x];
        idx[threadIdx.x] = d_idx[t * 32 + threadIdx.x];
    }
    __syncthreads();
    const float4* vt4 = (const float4*)vt;
    int d = threadIdx.x;
    float4 acc = {0.f, 0.f, 0.f, 0.f};
    #pragma unroll 4
    for (int e = 0; e < 32; e++) {
        float4 r = vt4[(size_t)idx[e] * 256 + d];
        float ww = w[e];
        acc.x = __fmaf_rn(ww, r.x, acc.x);
        acc.y = __fmaf_rn(ww, r.y, acc.y);
        acc.z = __fmaf_rn(ww, r.z, acc.z);
        acc.w = __fmaf_rn(ww, r.w, acc.w);
    }
    ((float4*)d_mem)[(size_t)t * 256 + d] = acc;
}

// ---------------- launch ----------------
extern "C" void kernel_launch(void* const* d_in, const int* in_sizes, int n_in,
                              void* d_out, int out_size)
{
    const float* x    = (const float*)d_in[0];
    const float* wq   = (const float*)d_in[1];
    const float* qnw  = (const float*)d_in[2];
    const float* keys = (const float*)d_in[3];
    const float* vt   = (const float*)d_in[4];
    const float* wsw  = (const float*)d_in[5];
    const float* wv   = (const float*)d_in[6];
    float* out = (float*)d_out;

    float *pq, *pscores, *pmem, *phbuf;
    cudaGetSymbolAddress((void**)&pq,      d_q);
    cudaGetSymbolAddress((void**)&pscores, d_scores);
    cudaGetSymbolAddress((void**)&pmem,    d_mem);
    cudaGetSymbolAddress((void**)&phbuf,   d_hbuf);

    // 1. q = x @ wq^T, split-K=2 single kernel (R11 bitwise order)
    sgemm128<1,64><<<dim3(QDIM/64, BS/128, 1), 256>>>(
        BS, QDIM, HDIM, x, HDIM, 0, wq, HDIM, 0, pq, QDIM, 0);

    // 2. layernorm (XLA order, frozen)
    qln_kernel<<<(BS*4)/4, 256>>>(qnw);

    // 3. score GEMMs, serial-k, batched z=4
    sgemm128<0,128><<<dim3(KNUM/128, BS/128, 4), 256>>>(
        BS, KNUM, KDIM,
        pq, QDIM, (long long)KDIM,
        keys, KDIM, (long long)KNUM*KDIM,
        pscores, KNUM, (long long)BS*KNUM);

    // 4-5. top-k stages (frozen)
    topk1_kernel<<<(4*BS*32)/256, 256>>>();
    topk2_kernel<<<(BS*HEADS)/8, 256>>>();

    // 6. gather
    gather_kernel<<<BS, 256>>>(vt);

    // 7-8. gate + output GEMMs (TF32 tensor cores)
    tf32gemm<1><<<dim3(HDIM/128, BS/128), 256>>>(
        BS, HDIM, HDIM, x, HDIM, wsw, HDIM, phbuf, HDIM, pmem);
    tf32gemm<0><<<dim3(HDIM/128, BS/128), 256>>>(
        BS, HDIM, HDIM, phbuf, HDIM, wv, HDIM, out, HDIM, nullptr);
}

// round 17
// speedup vs baseline: 1.6076x; 1.5318x over previous
#include <cuda_runtime.h>
#include <math.h>
#include <stdint.h>

#define HEADS 2
#define KDIM 128
#define KNN 16
#define KNUM 512
#define HDIM 1024
#define BS 4096
#define QDIM (KDIM*2*HEADS)   // 512

__device__ float d_q[BS*QDIM];
__device__ float d_scores[4*BS*KNUM];
__device__ float d_s1[4*BS*KNN];
__device__ int   d_i1[4*BS*KNN];
__device__ float d_w[BS*HEADS*KNN];
__device__ int   d_idx[BS*HEADS*KNN];
__device__ float d_mem[BS*HDIM];
__device__ float d_hbuf[BS*HDIM];

// =================================================================================
// FFMA SGEMM (selection path — BITWISE-FROZEN accumulation order). fma.rn.f32x2:
// each half is an exact IEEE fp32 FMA; serial ascending-k chain per output.
// SPLITK==1: two chains (k<K/2, k>=K/2), C = fadd(acc, acc2)  [R11 passing order]
// =================================================================================
template<int SPLITK, int BN>
__global__ __launch_bounds__(256, 2) void sgemm128(
    int M, int N, int K,
    const float* __restrict__ A, int lda, long long aBz,
    const float* __restrict__ B, int ldb, long long bBz,
    float* __restrict__ C, int ldc, long long cBz)
{
    constexpr int BK = 16;
    constexpr int TN = BN / 16;
    constexpr int TNP = TN / 2;
    constexpr int BPASS = BN / 64;
    __shared__ __align__(16) float As[2][BK][132];
    __shared__ __align__(16) float Bs[2][BK][BN + 4];

    const int tid = threadIdx.x;
    const int tx = tid & 15, ty = tid >> 4;
    const int bm = blockIdx.y * 128, bn = blockIdx.x * BN;
    const int z = blockIdx.z;
    const float* Ab = A + (size_t)z * aBz;
    const float* Bb = B + (size_t)z * bBz;
    float*       Cb = C + (size_t)z * cBz;
    const int lr = tid >> 2, lc4 = (tid & 3) * 4;

    unsigned long long acc[8][TNP];
    unsigned long long acc2[SPLITK ? 8 : 1][SPLITK ? TNP : 1];
    #pragma unroll
    for (int i = 0; i < 8; i++)
        #pragma unroll
        for (int p = 0; p < TNP; p++) acc[i][p] = 0ull;
    if (SPLITK) {
        #pragma unroll
        for (int i = 0; i < 8; i++)
            #pragma unroll
            for (int p = 0; p < TNP; p++) acc2[i][p] = 0ull;
    }

    float4 pa0, pa1, pb[BPASS];
    auto gload = [&](int k0) {
        pa0 = *(const float4*)&Ab[(size_t)(bm + lr)      * lda + k0 + lc4];
        pa1 = *(const float4*)&Ab[(size_t)(bm + lr + 64) * lda + k0 + lc4];
        #pragma unroll
        for (int p = 0; p < BPASS; p++)
            pb[p] = *(const float4*)&Bb[(size_t)(bn + lr + p*64) * ldb + k0 + lc4];
    };
    auto sstore = [&](int buf) {
        As[buf][lc4+0][lr] = pa0.x; As[buf][lc4+1][lr] = pa0.y;
        As[buf][lc4+2][lr] = pa0.z; As[buf][lc4+3][lr] = pa0.w;
        As[buf][lc4+0][lr+64] = pa1.x; As[buf][lc4+1][lr+64] = pa1.y;
        As[buf][lc4+2][lr+64] = pa1.z; As[buf][lc4+3][lr+64] = pa1.w;
        #pragma unroll
        for (int p = 0; p < BPASS; p++) {
            Bs[buf][lc4+0][lr + p*64] = pb[p].x;
            Bs[buf][lc4+1][lr + p*64] = pb[p].y;
            Bs[buf][lc4+2][lr + p*64] = pb[p].z;
            Bs[buf][lc4+3][lr + p*64] = pb[p].w;
        }
    };

    gload(0); sstore(0); __syncthreads();
    const int nt = K / BK;
    const int ntHalf = nt >> 1;
    for (int t = 0; t < nt; t++) {
        const int buf = t & 1;
        if (t + 1 < nt) gload((t + 1) * BK);
        const bool second = SPLITK && (t >= ntHalf);
        #pragma unroll
        for (int kk = 0; kk < BK; kk++) {
            float av[8];
            *(float4*)&av[0] = *(const float4*)&As[buf][kk][ty*8];
            *(float4*)&av[4] = *(const float4*)&As[buf][kk][ty*8 + 4];
            unsigned long long ap[8];
            #pragma unroll
            for (int i = 0; i < 8; i++)
                asm("mov.b64 %0, {%1, %1};" : "=l"(ap[i]) : "r"(__float_as_uint(av[i])));
            unsigned long long bp[TNP];
            const unsigned long long* bq =
                reinterpret_cast<const unsigned long long*>(&Bs[buf][kk][tx*TN]);
            #pragma unroll
            for (int p = 0; p < TNP; p++) bp[p] = bq[p];
            if (!second) {
                #pragma unroll
                for (int i = 0; i < 8; i++)
                    #pragma unroll
                    for (int p = 0; p < TNP; p++)
                        asm("fma.rn.f32x2 %0, %1, %2, %0;"
                            : "+l"(acc[i][p]) : "l"(ap[i]), "l"(bp[p]));
            } else {
                #pragma unroll
                for (int i = 0; i < 8; i++)
                    #pragma unroll
                    for (int p = 0; p < TNP; p++)
                        asm("fma.rn.f32x2 %0, %1, %2, %0;"
                            : "+l"(acc2[i][p]) : "l"(ap[i]), "l"(bp[p]));
            }
        }
        if (t + 1 < nt) { sstore(buf ^ 1); }
        __syncthreads();
    }

    #pragma unroll
    for (int i = 0; i < 8; i++) {
        int row = bm + ty*8 + i;
        #pragma unroll
        for (int p = 0; p < TNP; p++) {
            int col = bn + tx*TN + 2*p;
            float2 f = *(float2*)&acc[i][p];
            if (SPLITK) {
                float2 g = *(float2*)&acc2[i][p];
                f.x = __fadd_rn(f.x, g.x);
                f.y = __fadd_rn(f.y, g.y);
            }
            *(float2*)&Cb[(size_t)row * ldc + col] = f;
        }
    }
}

// ================= TF32 tensor-core GEMM (gate/out; smooth ~2e-4) ================
__device__ __forceinline__ uint32_t f2tf32(float x) {
    uint32_t u;
    asm("cvt.rna.tf32.f32 %0, %1;" : "=r"(u) : "f"(x));
    return u;
}

template<int EPI>
__global__ __launch_bounds__(256) void tf32gemm(
    int M, int N, int K,
    const float* __restrict__ A, int lda,
    const float* __restrict__ B, int ldb,
    float* __restrict__ C, int ldc,
    const float* __restrict__ other)
{
    constexpr int BK = 16;
    __shared__ uint32_t Asm[2][128][20];
    __shared__ uint32_t Bsm[2][BK][136];

    const int tid  = threadIdx.x;
    const int lane = tid & 31;
    const int wid  = tid >> 5;
    const int wm   = wid & 3;
    const int wn   = wid >> 2;
    const int r    = lane >> 2;
    const int c    = lane & 3;
    const int bm = blockIdx.y * 128, bn = blockIdx.x * 128;
    const int lr = tid >> 2, lc4 = (tid & 3) * 4;

    float d[2][8][4];
    #pragma unroll
    for (int mi = 0; mi < 2; mi++)
        #pragma unroll
        for (int nj = 0; nj < 8; nj++)
            #pragma unroll
            for (int q = 0; q < 4; q++) d[mi][nj][q] = 0.f;

    float4 fa0, fa1, fb0, fb1;
    auto gload = [&](int k0) {
        fa0 = *(const float4*)&A[(size_t)(bm + lr)      * lda + k0 + lc4];
        fa1 = *(const float4*)&A[(size_t)(bm + lr + 64) * lda + k0 + lc4];
        fb0 = *(const float4*)&B[(size_t)(bn + lr)      * ldb + k0 + lc4];
        fb1 = *(const float4*)&B[(size_t)(bn + lr + 64) * ldb + k0 + lc4];
    };
    auto sstore = [&](int buf) {
        uint4 ua0 = { f2tf32(fa0.x), f2tf32(fa0.y), f2tf32(fa0.z), f2tf32(fa0.w) };
        uint4 ua1 = { f2tf32(fa1.x), f2tf32(fa1.y), f2tf32(fa1.z), f2tf32(fa1.w) };
        *(uint4*)&Asm[buf][lr][lc4]      = ua0;
        *(uint4*)&Asm[buf][lr + 64][lc4] = ua1;
        Bsm[buf][lc4+0][lr] = f2tf32(fb0.x);
        Bsm[buf][lc4+1][lr] = f2tf32(fb0.y);
        Bsm[buf][lc4+2][lr] = f2tf32(fb0.z);
        Bsm[buf][lc4+3][lr] = f2tf32(fb0.w);
        Bsm[buf][lc4+0][lr+64] = f2tf32(fb1.x);
        Bsm[buf][lc4+1][lr+64] = f2tf32(fb1.y);
        Bsm[buf][lc4+2][lr+64] = f2tf32(fb1.z);
        Bsm[buf][lc4+3][lr+64] = f2tf32(fb1.w);
    };

    gload(0); sstore(0); __syncthreads();
    const int nt = K / BK;
    for (int t = 0; t < nt; t++) {
        const int buf = t & 1;
        if (t + 1 < nt) gload((t + 1) * BK);
        #pragma unroll
        for (int ks = 0; ks < BK; ks += 8) {
            uint32_t afr[2][4], bfr[8][2];
            #pragma unroll
            for (int mi = 0; mi < 2; mi++) {
                int m0 = wm*32 + mi*16;
                afr[mi][0] = Asm[buf][m0 + r    ][ks + c];
                afr[mi][1] = Asm[buf][m0 + r + 8][ks + c];
                afr[mi][2] = Asm[buf][m0 + r    ][ks + c + 4];
                afr[mi][3] = Asm[buf][m0 + r + 8][ks + c + 4];
            }
            #pragma unroll
            for (int nj = 0; nj < 8; nj++) {
                int n0 = wn*64 + nj*8 + r;
                bfr[nj][0] = Bsm[buf][ks + c    ][n0];
                bfr[nj][1] = Bsm[buf][ks + c + 4][n0];
            }
            #pragma unroll
            for (int mi = 0; mi < 2; mi++)
                #pragma unroll
                for (int nj = 0; nj < 8; nj++) {
                    asm volatile(
                        "mma.sync.aligned.m16n8k8.row.col.f32.tf32.tf32.f32 "
                        "{%0,%1,%2,%3}, {%4,%5,%6,%7}, {%8,%9}, {%0,%1,%2,%3};"
                        : "+f"(d[mi][nj][0]), "+f"(d[mi][nj][1]),
                          "+f"(d[mi][nj][2]), "+f"(d[mi][nj][3])
                        : "r"(afr[mi][0]), "r"(afr[mi][1]),
                          "r"(afr[mi][2]), "r"(afr[mi][3]),
                          "r"(bfr[nj][0]), "r"(bfr[nj][1]));
                }
        }
        if (t + 1 < nt) { sstore(buf ^ 1); }
        __syncthreads();
    }

    #pragma unroll
    for (int mi = 0; mi < 2; mi++) {
        #pragma unroll
        for (int nj = 0; nj < 8; nj++) {
            int col = bn + wn*64 + nj*8 + c*2;
            #pragma unroll
            for (int half = 0; half < 2; half++) {
                int row = bm + wm*32 + mi*16 + r + half*8;
                float v0 = d[mi][nj][half*2 + 0];
                float v1 = d[mi][nj][half*2 + 1];
                if (EPI == 1) {
                    const float2 o = *(const float2*)&other[(size_t)row * ldc + col];
                    float s0 = v0 / (1.0f + expf(-v0));
                    float s1 = v1 / (1.0f + expf(-v1));
                    v0 = s0 * o.x;
                    v1 = s1 * o.y;
                }
                float2 res = { v0, v1 };
                *(float2*)&C[(size_t)row * ldc + col] = res;
            }
        }
    }
}

// ------------- per-128 LayerNorm (XLA order) — BITWISE-FROZEN --------------------
__global__ __launch_bounds__(256) void qln_kernel(const float* __restrict__ gamma)
{
    __shared__ float s_w[4][2];
    int tid = threadIdx.x;
    int r = tid >> 6;
    int tx = tid & 63;
    int lane = tid & 31;
    int wIn = (tid >> 5) & 1;
    size_t row = (size_t)blockIdx.x * 4 + r;
    float* p = d_q + row * 128;
    float x0 = p[2*tx], x1 = p[2*tx+1];

    float part = __fadd_rn(x0, x1);
    #pragma unroll
    for (int o = 16; o; o >>= 1)
        part = __fadd_rn(part, __shfl_down_sync(0xffffffffu, part, o));
    if (lane == 0) s_w[r][wIn] = part;
    __syncthreads();
    float mu = __fmul_rn(__fadd_rn(s_w[r][0], s_w[r][1]), 1.0f/128.0f);
    __syncthreads();

    float d0 = __fsub_rn(x0, mu), d1 = __fsub_rn(x1, mu);
    float vp = __fadd_rn(__fmul_rn(d0, d0), __fmul_rn(d1, d1));
    #pragma unroll
    for (int o = 16; o; o >>= 1)
        vp = __fadd_rn(vp, __shfl_down_sync(0xffffffffu, vp, o));
    if (lane == 0) s_w[r][wIn] = vp;
    __syncthreads();
    float var = __fmul_rn(__fadd_rn(s_w[r][0], s_w[r][1]), 1.0f/128.0f);

    float denom = __fsqrt_rn(__fadd_rn(var, 1e-5f));
    p[2*tx]   = __fmul_rn(__fdiv_rn(d0, denom), gamma[2*tx]);
    p[2*tx+1] = __fmul_rn(__fdiv_rn(d1, denom), gamma[2*tx+1]);
}

// =================================================================================
// topk1: top-16 of 512, SAME RESULT as frozen iterative argmax (value desc, lowest
// gidx on ties). Keys k = (ordu(v)<<32)|(511-gidx): desc key order == frozen order.
// Per-lane Batcher sort-16 once, spill to smem, then 16 extractions via redux.max.
// =================================================================================
__device__ __forceinline__ unsigned ordu(float f) {
    unsigned u = __float_as_uint(f);
    return u ^ (0x80000000u | (unsigned)((int)u >> 31));
}
__device__ __forceinline__ float unordu(unsigned m) {
    unsigned u = (m & 0x80000000u) ? (m ^ 0x80000000u) : ~m;
    return __uint_as_float(u);
}

__global__ __launch_bounds__(256) void topk1_kernel()
{
    __shared__ unsigned long long s_k[8][16][32];
    const int w = threadIdx.x >> 5, lane = threadIdx.x & 31;
    const int gw = blockIdx.x * 8 + w;
    const float* s = d_scores + (size_t)gw * 512;

    unsigned long long k[16];
    #pragma unroll
    for (int j = 0; j < 16; j++) {
        int gidx = lane + j * 32;
        k[j] = ((unsigned long long)ordu(s[gidx]) << 32) | (unsigned)(511 - gidx);
    }
    // Batcher odd-even mergesort, descending by u64 key (n=16)
    #pragma unroll
    for (int p = 1; p < 16; p <<= 1) {
        #pragma unroll
        for (int q = p; q >= 1; q >>= 1) {
            #pragma unroll
            for (int j = q % p; j + q < 16; j += 2*q) {
                #pragma unroll
                for (int i = 0; i < q; i++) {
                    int a = j + i, b = j + i + q;
                    if (b < 16 && (a / (2*p)) == (b / (2*p))) {
                        unsigned long long ka = k[a], kb = k[b];
                        bool sw = kb > ka;
                        k[a] = sw ? kb : ka;
                        k[b] = sw ? ka : kb;
                    }
                }
            }
        }
    }
    #pragma unroll
    for (int j = 0; j < 16; j++) s_k[w][j][lane] = k[j];
    __syncwarp();

    float* os = d_s1 + (size_t)gw * 16;
    int*   oi = d_i1 + (size_t)gw * 16;
    unsigned hv = (unsigned)(k[0] >> 32);
    unsigned lv = (unsigned)k[0];
    int head = 1;
    #pragma unroll
    for (int it = 0; it < 16; it++) {
        unsigned m  = __reduce_max_sync(0xffffffffu, hv);
        unsigned sel = (hv == m) ? lv : 0u;
        unsigned l2 = __reduce_max_sync(0xffffffffu, sel);
        bool win = (hv == m) && (lv == l2);
        if (win) {
            os[it] = unordu(m);
            oi[it] = 511 - (int)lv;
            unsigned long long nk = (head < 16) ? s_k[w][head][lane] : 0ull;
            head++;
            hv = (unsigned)(nk >> 32);
            lv = (unsigned)nk;
        }
    }
}

// ------------- combine, top-16 of 256, softmax — BITWISE-FROZEN ------------------
__global__ void topk2_kernel()
{
    __shared__ float sh_s1[8][16], sh_s2[8][16], sh_sel[8][16];
    __shared__ int   sh_i1[8][16], sh_i2[8][16];
    int wIn = threadIdx.x >> 5, lane = threadIdx.x & 31;
    int inst = blockIdx.x * 8 + wIn;
    int t = inst >> 1, h = inst & 1;
    int hs1 = h * 2 + 0, hs2 = h * 2 + 1;
    if (lane < 16) {
        sh_s1[wIn][lane] = d_s1[((size_t)hs1 * BS + t) * 16 + lane];
        sh_i1[wIn][lane] = d_i1[((size_t)hs1 * BS + t) * 16 + lane];
        sh_s2[wIn][lane] = d_s1[((size_t)hs2 * BS + t) * 16 + lane];
        sh_i2[wIn][lane] = d_i1[((size_t)hs2 * BS + t) * 16 + lane];
    }
    __syncwarp();
    float v[8];
    #pragma unroll
    for (int j = 0; j < 8; j++) {
        int c = lane + j * 32;
        v[j] = __fadd_rn(sh_s1[wIn][c >> 4], sh_s2[wIn][c & 15]);
    }
    int wbase = t * (HEADS * KNN) + h * KNN;
    for (int it = 0; it < 16; it++) {
        float bv = -INFINITY; int bj = 0;
        #pragma unroll
        for (int j = 0; j < 8; j++)
            if (v[j] > bv) { bv = v[j]; bj = j; }
        int bc = lane + bj * 32;
        #pragma unroll
        for (int o = 16; o; o >>= 1) {
            float ov = __shfl_xor_sync(0xffffffffu, bv, o);
            int oc = __shfl_xor_sync(0xffffffffu, bc, o);
            if (ov > bv || (ov == bv && oc < bc)) { bv = ov; bc = oc; }
        }
        if (lane == 0) {
            sh_sel[wIn][it] = bv;
            d_idx[wbase + it] = sh_i1[wIn][bc >> 4] * KNUM + sh_i2[wIn][bc & 15];
        }
        #pragma unroll
        for (int j = 0; j < 8; j++)
            if (lane + j * 32 == bc) v[j] = -INFINITY;
    }
    __syncwarp();
    if (lane < 16) {
        float m = sh_sel[wIn][0];
        float e = expf(__fsub_rn(sh_sel[wIn][lane], m));
        float s = e;
        #pragma unroll
        for (int o = 8; o; o >>= 1) s = __fadd_rn(s, __shfl_xor_sync(0x0000ffffu, s, o));
        d_w[wbase + lane] = __fdiv_rn(e, s);
    }
}

// ------------- gather + weighted sum over values_table ---------------------------
__global__ __launch_bounds__(256) void gather_kernel(const float* __restrict__ vt)
{
    int t = blockIdx.x;
    __shared__ float w[32];
    __shared__ int idx[32];
    if (threadIdx.x < 32) {
        w[threadIdx.x] = d_w[t * 32 + threadIdx.x];
        idx[threadIdx.x] = d_idx[t * 32 + threadIdx.x];
    }
    __syncthreads();
    const float4* vt4 = (const float4*)vt;
    int d = threadIdx.x;
    float4 acc = {0.f, 0.f, 0.f, 0.f};
    #pragma unroll 4
    for (int e = 0; e < 32; e++) {
        float4 r = vt4[(size_t)idx[e] * 256 + d];
        float ww = w[e];
        acc.x = __fmaf_rn(ww, r.x, acc.x);
        acc.y = __fmaf_rn(ww, r.y, acc.y);
        acc.z = __fmaf_rn(ww, r.z, acc.z);
        acc.w = __fmaf_rn(ww, r.w, acc.w);
    }
    ((float4*)d_mem)[(size_t)t * 256 + d] = acc;
}

// ---------------- launch ----------------
extern "C" void kernel_launch(void* const* d_in, const int* in_sizes, int n_in,
                              void* d_out, int out_size)
{
    const float* x    = (const float*)d_in[0];
    const float* wq   = (const float*)d_in[1];
    const float* qnw  = (const float*)d_in[2];
    const float* keys = (const float*)d_in[3];
    const float* vt   = (const float*)d_in[4];
    const float* wsw  = (const float*)d_in[5];
    const float* wv   = (const float*)d_in[6];
    float* out = (float*)d_out;

    float *pq, *pscores, *pmem, *phbuf;
    cudaGetSymbolAddress((void**)&pq,      d_q);
    cudaGetSymbolAddress((void**)&pscores, d_scores);
    cudaGetSymbolAddress((void**)&pmem,    d_mem);
    cudaGetSymbolAddress((void**)&phbuf,   d_hbuf);

    sgemm128<1,64><<<dim3(QDIM/64, BS/128, 1), 256>>>(
        BS, QDIM, HDIM, x, HDIM, 0, wq, HDIM, 0, pq, QDIM, 0);

    qln_kernel<<<(BS*4)/4, 256>>>(qnw);

    sgemm128<0,128><<<dim3(KNUM/128, BS/128, 4), 256>>>(
        BS, KNUM, KDIM,
        pq, QDIM, (long long)KDIM,
        keys, KDIM, (long long)KNUM*KDIM,
        pscores, KNUM, (long long)BS*KNUM);

    topk1_kernel<<<(4*BS)/8, 256>>>();
    topk2_kernel<<<(BS*HEADS)/8, 256>>>();

    gather_kernel<<<BS, 256>>>(vt);

    tf32gemm<1><<<dim3(HDIM/128, BS/128), 256>>>(
        BS, HDIM, HDIM, x, HDIM, wsw, HDIM, phbuf, HDIM, pmem);
    tf32gemm<0><<<dim3(HDIM/128, BS/128), 256>>>(
        BS, HDIM, HDIM, phbuf, HDIM, wv, HDIM, out, HDIM, nullptr);
}